// round 2
// baseline (speedup 1.0000x reference)
#include <cuda_runtime.h>

// StackedLinear: out[b] = x[b] @ W[ls[b]*512 : +512]^T + bias[ls[b]*512 : +512]
// B=16384, IN=2048, OUT=512, C=8 (sizes read from in_sizes at launch).
//
// Round 2: fp32 baseline, with ls_indices dtype auto-detection (harness may
// deliver int32 or int64) and clamped expert ids (faults -> wrong answers).

#define OUTF 512
#define MAXB 32768
#define MAXC 16

#define BM 128
#define BN 128
#define BK 16
#define TM 8
#define TN 8
#define NTHREADS 256

__device__ int g_perm[MAXB];
__device__ int g_cnt[MAXC];
__device__ int g_off[MAXC + 1];
__device__ int g_cur[MAXC];
__device__ int g_is32;   // 1 if ls buffer is int32, 0 if int64

// ---------------- dtype detection ----------------
// If ls is int64 with small values, every odd int32 word is a zero high-word.
// If ls is int32, odd positions hold real indices (nonzero w.p. 7/8 each).

__global__ void k_detect_init() { g_is32 = 0; }

__global__ void k_detect(const int* __restrict__ ls32, int B) {
    int i = blockIdx.x * blockDim.x + threadIdx.x;
    int pos = 2 * i + 1;              // odd int32 positions within first B words
    if (pos < B && ls32[pos] != 0) atomicExch(&g_is32, 1);
}

__device__ __forceinline__ int load_idx(const void* ls, int i, int C) {
    int v;
    if (g_is32) v = ((const int*)ls)[i];
    else        v = (int)((const long long*)ls)[i];
    if (v < 0) v = 0;
    if (v >= C) v = C - 1;
    return v;
}

// ---------------- routing kernels ----------------

__global__ void k_zero(int C) {
    int t = threadIdx.x;
    if (t < C) { g_cnt[t] = 0; g_cur[t] = 0; }
}

__global__ void k_hist(const void* __restrict__ ls, int B, int C) {
    int i = blockIdx.x * blockDim.x + threadIdx.x;
    if (i < B) atomicAdd(&g_cnt[load_idx(ls, i, C)], 1);
}

__global__ void k_scan(int C) {
    if (threadIdx.x == 0 && blockIdx.x == 0) {
        int s = 0;
        for (int e = 0; e < C; e++) { g_off[e] = s; s += g_cnt[e]; }
        g_off[C] = s;
    }
}

__global__ void k_scatter(const void* __restrict__ ls, int B, int C) {
    int i = blockIdx.x * blockDim.x + threadIdx.x;
    if (i < B) {
        int e = load_idx(ls, i, C);
        int p = g_off[e] + atomicAdd(&g_cur[e], 1);
        if (p < MAXB) g_perm[p] = i;
    }
}

// ---------------- gathered-GEMM kernel ----------------
// grid: (OUTF/BN, ceil(B/BM), C). Blocks whose m-tile exceeds the expert's
// row count exit immediately.

__global__ __launch_bounds__(NTHREADS)
void k_gemm(const float* __restrict__ x,
            const float* __restrict__ W,
            const float* __restrict__ bias,
            float* __restrict__ out,
            int IN) {
    const int e   = blockIdx.z;
    const int cnt = g_cnt[e];
    const int m0  = blockIdx.y * BM;
    if (m0 >= cnt) return;
    const int n0  = blockIdx.x * BN;
    const int* perm = g_perm + g_off[e];

    __shared__ float As[BK][BM];   // As[k][m]
    __shared__ float Bs[BK][BN];   // Bs[k][n]

    const int tid = threadIdx.x;

    // ---- A-tile loader mapping: 128 rows x 16 k, float4 along k ----
    const int a_k4  = (tid & 3) * 4;   // k offset of this thread's float4
    const int a_row = tid >> 2;        // 0..63 (second row = +64)
    const int gm0 = m0 + a_row;
    const int gm1 = gm0 + 64;
    const bool p0 = (gm0 < cnt);
    const bool p1 = (gm1 < cnt);
    const float* ap0 = x + (size_t)(p0 ? perm[gm0] : 0) * IN;
    const float* ap1 = x + (size_t)(p1 ? perm[gm1] : 0) * IN;

    // ---- B-tile loader mapping: 128 n x 16 k, float4 along k ----
    const int b_k4 = (tid & 3) * 4;
    const int b_n  = tid >> 2;         // 0..63 (second n = +64)
    const float* wp0 = W + (size_t)(e * OUTF + n0 + b_n) * IN;
    const float* wp1 = wp0 + (size_t)64 * IN;

    // ---- compute mapping: 16x16 threads, each 8x8 outputs ----
    const int ty = tid >> 4;           // 0..15 -> rows ty*8..
    const int tx = tid & 15;           // 0..15 -> cols tx*8..

    float acc[TM][TN];
#pragma unroll
    for (int i = 0; i < TM; i++)
#pragma unroll
        for (int j = 0; j < TN; j++) acc[i][j] = 0.f;

    for (int k0 = 0; k0 < IN; k0 += BK) {
        // load A tile (gathered rows; zero-fill past cnt)
        {
            float4 v0 = make_float4(0.f, 0.f, 0.f, 0.f);
            float4 v1 = make_float4(0.f, 0.f, 0.f, 0.f);
            if (p0) v0 = *(const float4*)(ap0 + k0 + a_k4);
            if (p1) v1 = *(const float4*)(ap1 + k0 + a_k4);
            As[a_k4 + 0][a_row]      = v0.x;
            As[a_k4 + 1][a_row]      = v0.y;
            As[a_k4 + 2][a_row]      = v0.z;
            As[a_k4 + 3][a_row]      = v0.w;
            As[a_k4 + 0][a_row + 64] = v1.x;
            As[a_k4 + 1][a_row + 64] = v1.y;
            As[a_k4 + 2][a_row + 64] = v1.z;
            As[a_k4 + 3][a_row + 64] = v1.w;
        }
        // load B tile
        {
            float4 v0 = *(const float4*)(wp0 + k0 + b_k4);
            float4 v1 = *(const float4*)(wp1 + k0 + b_k4);
            Bs[b_k4 + 0][b_n]      = v0.x;
            Bs[b_k4 + 1][b_n]      = v0.y;
            Bs[b_k4 + 2][b_n]      = v0.z;
            Bs[b_k4 + 3][b_n]      = v0.w;
            Bs[b_k4 + 0][b_n + 64] = v1.x;
            Bs[b_k4 + 1][b_n + 64] = v1.y;
            Bs[b_k4 + 2][b_n + 64] = v1.z;
            Bs[b_k4 + 3][b_n + 64] = v1.w;
        }
        __syncthreads();

#pragma unroll
        for (int kk = 0; kk < BK; kk++) {
            float4 av0 = *(const float4*)&As[kk][ty * 8];
            float4 av1 = *(const float4*)&As[kk][ty * 8 + 4];
            float4 bv0 = *(const float4*)&Bs[kk][tx * 8];
            float4 bv1 = *(const float4*)&Bs[kk][tx * 8 + 4];
            float a[TM] = {av0.x, av0.y, av0.z, av0.w, av1.x, av1.y, av1.z, av1.w};
            float bb[TN] = {bv0.x, bv0.y, bv0.z, bv0.w, bv1.x, bv1.y, bv1.z, bv1.w};
#pragma unroll
            for (int i = 0; i < TM; i++)
#pragma unroll
                for (int j = 0; j < TN; j++)
                    acc[i][j] = fmaf(a[i], bb[j], acc[i][j]);
        }
        __syncthreads();
    }

    // bias for this thread's 8 columns
    float bv[TN];
    {
        const float* bp = bias + e * OUTF + n0 + tx * 8;
#pragma unroll
        for (int j = 0; j < TN; j++) bv[j] = bp[j];
    }

    // store (gathered rows)
#pragma unroll
    for (int i = 0; i < TM; i++) {
        int gm = m0 + ty * 8 + i;
        if (gm < cnt) {
            int r = perm[gm];
            float* o = out + (size_t)r * OUTF + n0 + tx * 8;
            float4 r0, r1;
            r0.x = acc[i][0] + bv[0]; r0.y = acc[i][1] + bv[1];
            r0.z = acc[i][2] + bv[2]; r0.w = acc[i][3] + bv[3];
            r1.x = acc[i][4] + bv[4]; r1.y = acc[i][5] + bv[5];
            r1.z = acc[i][6] + bv[6]; r1.w = acc[i][7] + bv[7];
            *(float4*)(o + 0) = r0;
            *(float4*)(o + 4) = r1;
        }
    }
}

// ---------------- launch ----------------

extern "C" void kernel_launch(void* const* d_in, const int* in_sizes, int n_in,
                              void* d_out, int out_size) {
    const float* x   = (const float*)d_in[0];
    const void*  ls  = d_in[1];
    const float* W   = (const float*)d_in[2];
    const float* bia = (const float*)d_in[3];
    float*       out = (float*)d_out;

    const int B  = in_sizes[1];
    const int IN = in_sizes[0] / B;
    const int C  = in_sizes[3] / OUTF;

    // dtype detection for ls (int32 vs int64)
    k_detect_init<<<1, 1>>>();
    k_detect<<<(B / 2 + 255) / 256, 256>>>((const int*)ls, B);

    // routing
    k_zero<<<1, 32>>>(C);
    k_hist<<<(B + 255) / 256, 256>>>(ls, B, C);
    k_scan<<<1, 32>>>(C);
    k_scatter<<<(B + 255) / 256, 256>>>(ls, B, C);

    // gathered GEMM
    dim3 grid(OUTF / BN, (B + BM - 1) / BM, C);
    k_gemm<<<grid, NTHREADS>>>(x, W, bia, out, IN);
}

// round 3
// speedup vs baseline: 2.9550x; 2.9550x over previous
#include <cuda_runtime.h>
#include <cstdint>

// StackedLinear: out[b] = x[b] @ W[ls[b]*512 : +512]^T + bias[ls[b]*512 : +512]
// Round 3: TF32 tensor-core gathered GEMM (mma.sync.m16n8k8) with 4-stage
// cp.async pipeline. Routing (histogram/scan/scatter) reused from round 2.

#define OUTF 512
#define MAXB 32768
#define MAXC 16

#define BM 128
#define BN 128
#define BK 32
#define STAGES 4
#define NTHREADS 256
#define SS 36                      // smem row stride in floats (BK+4, conflict-free)
#define TILE_FLOATS (BM * SS)      // per A or B tile: 4608 floats
#define STAGE_FLOATS (2 * TILE_FLOATS)
#define SMEM_BYTES (STAGES * STAGE_FLOATS * 4)

__device__ int g_perm[MAXB];
__device__ int g_cnt[MAXC];
__device__ int g_off[MAXC + 1];
__device__ int g_cur[MAXC];
__device__ int g_is32;

// ---------------- dtype detection (int32 vs int64 ls buffer) ----------------

__global__ void k_detect_init() { g_is32 = 0; }

__global__ void k_detect(const int* __restrict__ ls32, int B) {
    int i = blockIdx.x * blockDim.x + threadIdx.x;
    int pos = 2 * i + 1;
    if (pos < B && ls32[pos] != 0) atomicExch(&g_is32, 1);
}

__device__ __forceinline__ int load_idx(const void* ls, int i, int C) {
    int v;
    if (g_is32) v = ((const int*)ls)[i];
    else        v = (int)((const long long*)ls)[i];
    if (v < 0) v = 0;
    if (v >= C) v = C - 1;
    return v;
}

// ---------------- routing ----------------

__global__ void k_zero(int C) {
    int t = threadIdx.x;
    if (t < C) { g_cnt[t] = 0; g_cur[t] = 0; }
}

__global__ void k_hist(const void* __restrict__ ls, int B, int C) {
    __shared__ int h[MAXC];
    if (threadIdx.x < MAXC) h[threadIdx.x] = 0;
    __syncthreads();
    for (int i = blockIdx.x * blockDim.x + threadIdx.x; i < B;
         i += gridDim.x * blockDim.x)
        atomicAdd(&h[load_idx(ls, i, C)], 1);
    __syncthreads();
    if (threadIdx.x < C) atomicAdd(&g_cnt[threadIdx.x], h[threadIdx.x]);
}

__global__ void k_scan(int C) {
    if (threadIdx.x == 0 && blockIdx.x == 0) {
        int s = 0;
        for (int e = 0; e < C; e++) { g_off[e] = s; s += g_cnt[e]; }
        g_off[C] = s;
    }
}

__global__ void k_scatter(const void* __restrict__ ls, int B, int C) {
    int i = blockIdx.x * blockDim.x + threadIdx.x;
    if (i < B) {
        int e = load_idx(ls, i, C);
        int p = g_off[e] + atomicAdd(&g_cur[e], 1);
        if (p < MAXB) g_perm[p] = i;
    }
}

// ---------------- TF32 MMA helpers ----------------

__device__ __forceinline__ uint32_t f2tf(float v) {
    uint32_t r;
    asm("cvt.rna.tf32.f32 %0, %1;" : "=r"(r) : "f"(v));
    return r;
}

__device__ __forceinline__ void mma_tf32(float c[4], const uint32_t a[4],
                                         const uint32_t b[2]) {
    asm volatile(
        "mma.sync.aligned.m16n8k8.row.col.f32.tf32.tf32.f32 "
        "{%0,%1,%2,%3}, {%4,%5,%6,%7}, {%8,%9}, {%0,%1,%2,%3};"
        : "+f"(c[0]), "+f"(c[1]), "+f"(c[2]), "+f"(c[3])
        : "r"(a[0]), "r"(a[1]), "r"(a[2]), "r"(a[3]), "r"(b[0]), "r"(b[1]));
}

__device__ __forceinline__ void cp16(uint32_t dst, const void* src, bool pred) {
    int sz = pred ? 16 : 0;
    asm volatile("cp.async.cg.shared.global [%0], [%1], 16, %2;\n"
                 :: "r"(dst), "l"(src), "r"(sz));
}

// ---------------- gathered TF32 GEMM ----------------
// grid: (OUTF/BN, ceil(B/BM), C). Warp layout: 2 (m) x 4 (n); warp tile 64x32.

__global__ __launch_bounds__(NTHREADS)
void k_gemm(const float* __restrict__ x,
            const float* __restrict__ W,
            const float* __restrict__ bias,
            float* __restrict__ out,
            int IN) {
    const int e   = blockIdx.z;
    const int cnt = g_cnt[e];
    const int m0  = blockIdx.y * BM;
    if (m0 >= cnt) return;
    const int n0  = blockIdx.x * BN;
    const int* perm = g_perm + g_off[e];

    extern __shared__ float smem[];
    const uint32_t smem_base = (uint32_t)__cvta_generic_to_shared(smem);

    const int tid  = threadIdx.x;
    const int lane = tid & 31;
    const int wid  = tid >> 5;
    const int warp_m = wid >> 2;      // 0..1
    const int warp_n = wid & 3;       // 0..3

    // ---- loader mapping: thread -> 4 rows (A and B), 1 16B chunk per row ----
    const int l_row0  = tid >> 3;     // 0..31 (+32 per pass)
    const int l_chunk = (tid & 7) * 4;

    const float* aptr[4];
    bool avalid[4];
    const float* bptr[4];
#pragma unroll
    for (int i = 0; i < 4; i++) {
        int gm = m0 + l_row0 + i * 32;
        avalid[i] = (gm < cnt);
        aptr[i] = x + (size_t)(avalid[i] ? perm[gm] : 0) * IN + l_chunk;
        bptr[i] = W + (size_t)(e * OUTF + n0 + l_row0 + i * 32) * IN + l_chunk;
    }
    // smem byte offsets (within a stage) for this thread's stores
    uint32_t a_soff[4], b_soff[4];
#pragma unroll
    for (int i = 0; i < 4; i++) {
        a_soff[i] = (uint32_t)(((l_row0 + i * 32) * SS + l_chunk) * 4);
        b_soff[i] = (uint32_t)((TILE_FLOATS + (l_row0 + i * 32) * SS + l_chunk) * 4);
    }

    const int KT = IN / BK;

    // ---- prologue: prefetch STAGES-1 tiles ----
#pragma unroll
    for (int s = 0; s < STAGES - 1; s++) {
        uint32_t sb = smem_base + (uint32_t)(s * STAGE_FLOATS * 4);
        int k0 = s * BK;
#pragma unroll
        for (int i = 0; i < 4; i++) {
            cp16(sb + a_soff[i], aptr[i] + k0, avalid[i]);
            cp16(sb + b_soff[i], bptr[i] + k0, true);
        }
        asm volatile("cp.async.commit_group;");
    }

    float acc[4][4][4];
#pragma unroll
    for (int mi = 0; mi < 4; mi++)
#pragma unroll
        for (int nj = 0; nj < 4; nj++)
#pragma unroll
            for (int q = 0; q < 4; q++) acc[mi][nj][q] = 0.f;

    const int fr = lane >> 2;         // fragment row within 8
    const int fk = lane & 3;          // fragment k within 4

    for (int kt = 0; kt < KT; kt++) {
        asm volatile("cp.async.wait_group %0;" :: "n"(STAGES - 2));
        __syncthreads();

        // issue load for tile kt+STAGES-1 into the stage freed by iter kt-1
        if (kt + STAGES - 1 < KT) {
            int s = (kt + STAGES - 1) % STAGES;
            uint32_t sb = smem_base + (uint32_t)(s * STAGE_FLOATS * 4);
            int k0 = (kt + STAGES - 1) * BK;
#pragma unroll
            for (int i = 0; i < 4; i++) {
                cp16(sb + a_soff[i], aptr[i] + k0, avalid[i]);
                cp16(sb + b_soff[i], bptr[i] + k0, true);
            }
        }
        asm volatile("cp.async.commit_group;");

        const float* As = smem + (kt % STAGES) * STAGE_FLOATS;
        const float* Bs = As + TILE_FLOATS;

#pragma unroll
        for (int ks = 0; ks < BK / 8; ks++) {
            const int kk = ks * 8 + fk;
            uint32_t af[4][4], bf[4][2];
#pragma unroll
            for (int mi = 0; mi < 4; mi++) {
                int row = warp_m * 64 + mi * 16 + fr;
                af[mi][0] = f2tf(As[row * SS + kk]);
                af[mi][1] = f2tf(As[(row + 8) * SS + kk]);
                af[mi][2] = f2tf(As[row * SS + kk + 4]);
                af[mi][3] = f2tf(As[(row + 8) * SS + kk + 4]);
            }
#pragma unroll
            for (int nj = 0; nj < 4; nj++) {
                int nn = warp_n * 32 + nj * 8 + fr;
                bf[nj][0] = f2tf(Bs[nn * SS + kk]);
                bf[nj][1] = f2tf(Bs[nn * SS + kk + 4]);
            }
#pragma unroll
            for (int mi = 0; mi < 4; mi++)
#pragma unroll
                for (int nj = 0; nj < 4; nj++)
                    mma_tf32(acc[mi][nj], af[mi], bf[nj]);
        }
        __syncthreads();
    }

    // ---- epilogue: bias + scattered store ----
    float bv[4][2];
#pragma unroll
    for (int nj = 0; nj < 4; nj++) {
        int col = n0 + warp_n * 32 + nj * 8 + 2 * fk;
        const float* bp = bias + e * OUTF + col;
        bv[nj][0] = bp[0];
        bv[nj][1] = bp[1];
    }

#pragma unroll
    for (int mi = 0; mi < 4; mi++) {
        int gm_lo = m0 + warp_m * 64 + mi * 16 + fr;
        int gm_hi = gm_lo + 8;
        if (gm_lo < cnt) {
            float* o = out + (size_t)perm[gm_lo] * OUTF + n0 + warp_n * 32;
#pragma unroll
            for (int nj = 0; nj < 4; nj++) {
                float2 v = make_float2(acc[mi][nj][0] + bv[nj][0],
                                       acc[mi][nj][1] + bv[nj][1]);
                *(float2*)(o + nj * 8 + 2 * fk) = v;
            }
        }
        if (gm_hi < cnt) {
            float* o = out + (size_t)perm[gm_hi] * OUTF + n0 + warp_n * 32;
#pragma unroll
            for (int nj = 0; nj < 4; nj++) {
                float2 v = make_float2(acc[mi][nj][2] + bv[nj][0],
                                       acc[mi][nj][3] + bv[nj][1]);
                *(float2*)(o + nj * 8 + 2 * fk) = v;
            }
        }
    }
}

// ---------------- launch ----------------

extern "C" void kernel_launch(void* const* d_in, const int* in_sizes, int n_in,
                              void* d_out, int out_size) {
    const float* x   = (const float*)d_in[0];
    const void*  ls  = d_in[1];
    const float* W   = (const float*)d_in[2];
    const float* bia = (const float*)d_in[3];
    float*       out = (float*)d_out;

    const int B  = in_sizes[1];
    const int IN = in_sizes[0] / B;
    const int C  = in_sizes[3] / OUTF;

    // dtype detection
    k_detect_init<<<1, 1>>>();
    k_detect<<<(B / 2 + 255) / 256, 256>>>((const int*)ls, B);

    // routing
    k_zero<<<1, 32>>>(C);
    k_hist<<<32, 256>>>(ls, B, C);
    k_scan<<<1, 32>>>(C);
    k_scatter<<<(B + 255) / 256, 256>>>(ls, B, C);

    // gathered TF32 GEMM
    static bool attr_set = false;
    if (!attr_set) {
        cudaFuncSetAttribute(k_gemm, cudaFuncAttributeMaxDynamicSharedMemorySize,
                             SMEM_BYTES);
        attr_set = true;
    }
    dim3 grid(OUTF / BN, (B + BM - 1) / BM, C);
    k_gemm<<<grid, NTHREADS, SMEM_BYTES>>>(x, W, bia, out, IN);
}